// round 1
// baseline (speedup 1.0000x reference)
#include <cuda_runtime.h>

// CategoryAwareGate: B=8, C=16, H=W=256, HID=32, N = B*H*W = 524288.
// Outputs packed in d_out (float32): fused_logits[8,16,256,256] (8388608),
// expert_preferences[16,2] (32), dynamic_weights[N,16,2] (16777216).
//
// Math: per pixel n, class c:
//   sp = softmax_C(swin)[c], gp = softmax_C(gru)[c]
//   hid_h = relu(W1[c,h,0]*sp + W1[c,h,1]*gp + b1[c,h])
//   d = (b2[c,0]-b2[c,1]) + sum_h (W2[c,0,h]-W2[c,1,h]) * hid_h   // z0 - z1
//   dw0 = sigmoid(d) == softmax([z0,z1])[0]; dw1 = 1 - dw0
//   fused[c] = gl + dw0*(sl - gl)
// Classes processed in pairs via packed fp32x2 FMA (fma.rn.f32x2).

static constexpr long FUSED_ELEMS = 8L * 16 * 65536;  // 8388608

__device__ __forceinline__ unsigned long long pk2(float a, float b) {
    unsigned long long r;
    asm("mov.b64 %0, {%1, %2};" : "=l"(r) : "f"(a), "f"(b));
    return r;
}
__device__ __forceinline__ void upk2(unsigned long long v, float& a, float& b) {
    asm("mov.b64 {%0, %1}, %2;" : "=f"(a), "=f"(b) : "l"(v));
}
__device__ __forceinline__ unsigned long long fma2(unsigned long long a,
                                                   unsigned long long b,
                                                   unsigned long long c) {
    unsigned long long r;
    asm("fma.rn.f32x2 %0, %1, %2, %3;" : "=l"(r) : "l"(a), "l"(b), "l"(c));
    return r;
}

__global__ void __launch_bounds__(256)
gate_fuse_kernel(const float* __restrict__ swin, const float* __restrict__ gru,
                 const float* __restrict__ W1, const float* __restrict__ b1,
                 const float* __restrict__ W2, const float* __restrict__ b2,
                 float* __restrict__ fused, float* __restrict__ dw) {
    // Packed per-(class-pair p, h) weights: [w10 pair][w11 pair][b1 pair][w2diff pair]
    __shared__ __align__(16) unsigned long long sw[8 * 32 * 4];  // 8 KB
    __shared__ float sb2d[16];

    const int tid = threadIdx.x;
    for (int idx = tid; idx < 8 * 32; idx += 256) {
        const int p = idx >> 5, h = idx & 31;
        const int c0 = p * 2, c1 = p * 2 + 1;
        // W1: (C,32,2) -> c*64 + h*2 + i ; b1: (C,32) ; W2: (C,2,32) -> c*64 + o*32 + h
        sw[idx * 4 + 0] = pk2(W1[c0 * 64 + h * 2 + 0], W1[c1 * 64 + h * 2 + 0]);
        sw[idx * 4 + 1] = pk2(W1[c0 * 64 + h * 2 + 1], W1[c1 * 64 + h * 2 + 1]);
        sw[idx * 4 + 2] = pk2(b1[c0 * 32 + h], b1[c1 * 32 + h]);
        sw[idx * 4 + 3] = pk2(W2[c0 * 64 + h] - W2[c0 * 64 + 32 + h],
                              W2[c1 * 64 + h] - W2[c1 * 64 + 32 + h]);
    }
    if (tid < 16) sb2d[tid] = b2[tid * 2] - b2[tid * 2 + 1];
    __syncthreads();

    const int n = blockIdx.x * 256 + tid;          // exact: grid = 2048 * 256 = N
    const int b = n >> 16;
    const int hw = n & 65535;
    const long base = (long)b * (16L * 65536) + hw;

    float sl[16], gl[16];
    float ms = -1e30f, mg = -1e30f;
#pragma unroll
    for (int c = 0; c < 16; c++) {
        sl[c] = __ldg(swin + base + (long)c * 65536);
        gl[c] = __ldg(gru + base + (long)c * 65536);
        ms = fmaxf(ms, sl[c]);
        mg = fmaxf(mg, gl[c]);
    }
    float ss = 0.f, sg = 0.f;
#pragma unroll
    for (int c = 0; c < 16; c++) {
        ss += __expf(sl[c] - ms);
        sg += __expf(gl[c] - mg);
    }
    const float rs = __fdividef(1.f, ss);
    const float rg = __fdividef(1.f, sg);

#pragma unroll
    for (int p = 0; p < 8; p++) {
        const int c0 = p * 2, c1 = c0 + 1;
        const float x0 = __expf(sl[c0] - ms) * rs;
        const float x1 = __expf(sl[c1] - ms) * rs;
        const float y0 = __expf(gl[c0] - mg) * rg;
        const float y1 = __expf(gl[c1] - mg) * rg;
        const unsigned long long xp = pk2(x0, x1);
        const unsigned long long yp = pk2(y0, y1);
        unsigned long long d2 = pk2(sb2d[c0], sb2d[c1]);
        const unsigned long long* wp = sw + p * 32 * 4;
#pragma unroll
        for (int h = 0; h < 32; h++) {
            const ulonglong2 wA = *reinterpret_cast<const ulonglong2*>(wp + h * 4);
            const ulonglong2 wB = *reinterpret_cast<const ulonglong2*>(wp + h * 4 + 2);
            unsigned long long t = fma2(wA.x, xp, wB.x);
            t = fma2(wA.y, yp, t);
            float ta, tb;
            upk2(t, ta, tb);
            ta = fmaxf(ta, 0.f);
            tb = fmaxf(tb, 0.f);
            d2 = fma2(wB.y, pk2(ta, tb), d2);
        }
        float d0, d1;
        upk2(d2, d0, d1);
        const float w0a = __fdividef(1.f, 1.f + __expf(-d0));
        const float w0b = __fdividef(1.f, 1.f + __expf(-d1));
        float4 o;
        o.x = w0a;
        o.y = 1.f - w0a;
        o.z = w0b;
        o.w = 1.f - w0b;
        *reinterpret_cast<float4*>(dw + (long)n * 32 + p * 4) = o;
        fused[base + (long)c0 * 65536] = fmaf(w0a, sl[c0] - gl[c0], gl[c0]);
        fused[base + (long)c1 * 65536] = fmaf(w0b, sl[c1] - gl[c1], gl[c1]);
    }
}

extern "C" void kernel_launch(void* const* d_in, const int* in_sizes, int n_in,
                              void* d_out, int out_size) {
    const float* swin = (const float*)d_in[0];
    const float* gru  = (const float*)d_in[1];
    const float* W1   = (const float*)d_in[2];
    const float* b1   = (const float*)d_in[3];
    const float* W2   = (const float*)d_in[4];
    const float* b2   = (const float*)d_in[5];
    const float* pref = (const float*)d_in[6];

    float* out     = (float*)d_out;
    float* fused   = out;                       // 8388608
    float* prefout = out + FUSED_ELEMS;         // 32
    float* dw      = out + FUSED_ELEMS + 32;    // 16777216

    cudaMemcpyAsync(prefout, pref, 32 * sizeof(float), cudaMemcpyDeviceToDevice);
    gate_fuse_kernel<<<2048, 256>>>(swin, gru, W1, b1, W2, b2, fused, dw);
}

// round 2
// speedup vs baseline: 1.2217x; 1.2217x over previous
#include <cuda_runtime.h>

// CategoryAwareGate: B=8, C=16, H=W=256, HID=32, N = B*H*W = 524288.
// Outputs packed in d_out (float32): fused_logits[8,16,256,256] (8388608),
// expert_preferences[16,2] (32), dynamic_weights[N,16,2] (16777216).
//
// Per pixel n, class c:
//   sp = softmax_C(swin)[c], gp = softmax_C(gru)[c]          (no max-sub: |logit|<~6)
//   hid_h = relu(W1[c,h,0]*sp + W1[c,h,1]*gp + b1[c,h])
//   d = (b2[c,0]-b2[c,1]) + sum_h (W2[c,0,h]-W2[c,1,h])*hid_h   // z0 - z1
//   dw0 = sigmoid(d); dw1 = 1 - dw0; fused[c] = gl + dw0*(sl-gl)
//
// R2: 2 pixels/thread (weight-LDS amortized), dw stores transposed through
// padded smem so global stores are fully coalesced STG.128.

static constexpr long FUSED_ELEMS = 8L * 16 * 65536;  // 8388608
// dynamic smem: 1024 u64 packed weights (8KB) + 16 b2diff (+pad to 64B)
//             + 2 slots * 8 warps * 32 px * 36 floats (transpose buffers)
static constexpr int TB_STRIDE = 36;                     // words per pixel row (pad: bank-conflict-free)
static constexpr int TB_WARP   = 32 * TB_STRIDE;         // 1152 floats per warp-slot
static constexpr int SMEM_BYTES = 8192 + 64 + 2 * 8 * TB_WARP * 4;  // 81984

__device__ __forceinline__ unsigned long long pk2(float a, float b) {
    unsigned long long r;
    asm("mov.b64 %0, {%1, %2};" : "=l"(r) : "f"(a), "f"(b));
    return r;
}
__device__ __forceinline__ void upk2(unsigned long long v, float& a, float& b) {
    asm("mov.b64 {%0, %1}, %2;" : "=f"(a), "=f"(b) : "l"(v));
}
__device__ __forceinline__ unsigned long long fma2(unsigned long long a,
                                                   unsigned long long b,
                                                   unsigned long long c) {
    unsigned long long r;
    asm("fma.rn.f32x2 %0, %1, %2, %3;" : "=l"(r) : "l"(a), "l"(b), "l"(c));
    return r;
}

__global__ void __launch_bounds__(256, 2)
gate_fuse_kernel(const float* __restrict__ swin, const float* __restrict__ gru,
                 const float* __restrict__ W1, const float* __restrict__ b1,
                 const float* __restrict__ W2, const float* __restrict__ b2,
                 float* __restrict__ fused, float* __restrict__ dw) {
    extern __shared__ __align__(16) unsigned char smem_raw[];
    unsigned long long* sw = reinterpret_cast<unsigned long long*>(smem_raw);  // 1024 u64
    float* sb2d = reinterpret_cast<float*>(smem_raw + 8192);                   // 16 floats
    float* tb   = reinterpret_cast<float*>(smem_raw + 8192 + 64);

    const int tid = threadIdx.x;
    const int warp = tid >> 5;
    const int lane = tid & 31;

    // Pack per-(class-pair p, h): [w10 pair][w11 pair][b1 pair][w2diff pair]
    {
        const int p = tid >> 5, h = tid & 31;   // 8*32 == blockDim: one entry per thread
        const int c0 = p * 2, c1 = c0 + 1;
        // W1:(C,32,2) c*64+h*2+i ; b1:(C,32) ; W2:(C,2,32) c*64+o*32+h
        sw[tid * 4 + 0] = pk2(W1[c0 * 64 + h * 2 + 0], W1[c1 * 64 + h * 2 + 0]);
        sw[tid * 4 + 1] = pk2(W1[c0 * 64 + h * 2 + 1], W1[c1 * 64 + h * 2 + 1]);
        sw[tid * 4 + 2] = pk2(b1[c0 * 32 + h], b1[c1 * 32 + h]);
        sw[tid * 4 + 3] = pk2(W2[c0 * 64 + h] - W2[c0 * 64 + 32 + h],
                              W2[c1 * 64 + h] - W2[c1 * 64 + 32 + h]);
    }
    if (tid < 16) sb2d[tid] = b2[tid * 2] - b2[tid * 2 + 1];
    __syncthreads();

    // Two pixel slots per thread, 256 apart (each slot stays fully coalesced).
    const int n0 = blockIdx.x * 512 + tid;   // grid 1024 * 512 px = N; never straddles batch
    const int n1 = n0 + 256;
    const long base0 = (long)(n0 >> 16) * (16L * 65536) + (n0 & 65535);
    const long base1 = (long)(n1 >> 16) * (16L * 65536) + (n1 & 65535);

    float sl0[16], gl0[16], sl1[16], gl1[16];
    float ss0 = 0.f, sg0 = 0.f, ss1 = 0.f, sg1 = 0.f;
#pragma unroll
    for (int c = 0; c < 16; c++) {
        sl0[c] = __ldg(swin + base0 + (long)c * 65536);
        gl0[c] = __ldg(gru  + base0 + (long)c * 65536);
        sl1[c] = __ldg(swin + base1 + (long)c * 65536);
        gl1[c] = __ldg(gru  + base1 + (long)c * 65536);
        ss0 += __expf(sl0[c]); sg0 += __expf(gl0[c]);
        ss1 += __expf(sl1[c]); sg1 += __expf(gl1[c]);
    }
    const float rs0 = __fdividef(1.f, ss0), rg0 = __fdividef(1.f, sg0);
    const float rs1 = __fdividef(1.f, ss1), rg1 = __fdividef(1.f, sg1);

    float* tb0 = tb + warp * TB_WARP;                // slot 0 transpose buffer
    float* tb1 = tb + 8 * TB_WARP + warp * TB_WARP;  // slot 1

#pragma unroll
    for (int p = 0; p < 8; p++) {
        const int c0 = 2 * p, c1 = c0 + 1;
        const unsigned long long xp0 = pk2(__expf(sl0[c0]) * rs0, __expf(sl0[c1]) * rs0);
        const unsigned long long yp0 = pk2(__expf(gl0[c0]) * rg0, __expf(gl0[c1]) * rg0);
        const unsigned long long xp1 = pk2(__expf(sl1[c0]) * rs1, __expf(sl1[c1]) * rs1);
        const unsigned long long yp1 = pk2(__expf(gl1[c0]) * rg1, __expf(gl1[c1]) * rg1);
        unsigned long long d20 = pk2(sb2d[c0], sb2d[c1]);
        unsigned long long d21 = d20;
        const unsigned long long* wp = sw + p * 128;
#pragma unroll
        for (int h = 0; h < 32; h++) {
            const ulonglong2 wA = *reinterpret_cast<const ulonglong2*>(wp + h * 4);
            const ulonglong2 wB = *reinterpret_cast<const ulonglong2*>(wp + h * 4 + 2);
            unsigned long long t0 = fma2(wA.x, xp0, wB.x);
            t0 = fma2(wA.y, yp0, t0);
            unsigned long long t1 = fma2(wA.x, xp1, wB.x);
            t1 = fma2(wA.y, yp1, t1);
            float a, bv;
            upk2(t0, a, bv);
            a = fmaxf(a, 0.f); bv = fmaxf(bv, 0.f);
            d20 = fma2(wB.y, pk2(a, bv), d20);
            upk2(t1, a, bv);
            a = fmaxf(a, 0.f); bv = fmaxf(bv, 0.f);
            d21 = fma2(wB.y, pk2(a, bv), d21);
        }
        float d0a, d0b, d1a, d1b;
        upk2(d20, d0a, d0b);
        upk2(d21, d1a, d1b);
        const float w00 = __fdividef(1.f, 1.f + __expf(-d0a));
        const float w01 = __fdividef(1.f, 1.f + __expf(-d0b));
        const float w10 = __fdividef(1.f, 1.f + __expf(-d1a));
        const float w11 = __fdividef(1.f, 1.f + __expf(-d1b));
        // stage dw in smem (stride-36 rows: STS.128 conflict-free)
        *reinterpret_cast<float4*>(tb0 + lane * TB_STRIDE + p * 4) =
            make_float4(w00, 1.f - w00, w01, 1.f - w01);
        *reinterpret_cast<float4*>(tb1 + lane * TB_STRIDE + p * 4) =
            make_float4(w10, 1.f - w10, w11, 1.f - w11);
        // fused: lanes consecutive within a class plane -> coalesced STG.32
        fused[base0 + (long)c0 * 65536] = fmaf(w00, sl0[c0] - gl0[c0], gl0[c0]);
        fused[base0 + (long)c1 * 65536] = fmaf(w01, sl0[c1] - gl0[c1], gl0[c1]);
        fused[base1 + (long)c0 * 65536] = fmaf(w10, sl1[c0] - gl1[c0], gl1[c0]);
        fused[base1 + (long)c1 * 65536] = fmaf(w11, sl1[c1] - gl1[c1], gl1[c1]);
    }

    __syncwarp();
    // Drain dw coalesced: warp-slot chunk = 32 px * 32 floats = 4KB contiguous.
    {
        const long g0 = ((long)blockIdx.x * 512 + warp * 32) * 32;
        const long g1 = g0 + 256L * 32;
#pragma unroll
        for (int k = 0; k < 8; k++) {
            const int pix  = 4 * k + (lane >> 3);
            const int elem = (lane & 7) * 4;
            const float4 v0 = *reinterpret_cast<const float4*>(tb0 + pix * TB_STRIDE + elem);
            const float4 v1 = *reinterpret_cast<const float4*>(tb1 + pix * TB_STRIDE + elem);
            *reinterpret_cast<float4*>(dw + g0 + k * 128 + lane * 4) = v0;
            *reinterpret_cast<float4*>(dw + g1 + k * 128 + lane * 4) = v1;
        }
    }
}

extern "C" void kernel_launch(void* const* d_in, const int* in_sizes, int n_in,
                              void* d_out, int out_size) {
    const float* swin = (const float*)d_in[0];
    const float* gru  = (const float*)d_in[1];
    const float* W1   = (const float*)d_in[2];
    const float* b1   = (const float*)d_in[3];
    const float* W2   = (const float*)d_in[4];
    const float* b2   = (const float*)d_in[5];
    const float* pref = (const float*)d_in[6];

    float* out     = (float*)d_out;
    float* fused   = out;                     // 8388608
    float* prefout = out + FUSED_ELEMS;       // 32
    float* dw      = out + FUSED_ELEMS + 32;  // 16777216

    cudaFuncSetAttribute(gate_fuse_kernel,
                         cudaFuncAttributeMaxDynamicSharedMemorySize, SMEM_BYTES);
    cudaMemcpyAsync(prefout, pref, 32 * sizeof(float), cudaMemcpyDeviceToDevice);
    gate_fuse_kernel<<<1024, 256, SMEM_BYTES>>>(swin, gru, W1, b1, W2, b2, fused, dw);
}